// round 2
// baseline (speedup 1.0000x reference)
#include <cuda_runtime.h>
#include <math.h>

#define SCALE_Q 0.17677669529663687f

// scratch (device globals, aliased across phases)
__device__ float g_tok[25165824];    // xw -> attn_out -> h2   (131072 x 192)
__device__ float g_big[100663296];   // qkv -> hid             (131072 x 576/768)
__device__ float g_x2v[25165824];    // x after attn residual  (B,C,H,W)
__device__ float g_M[2][32][4096];   // per-batch 64x64 patch conv matrices
__device__ float2 g_gn[2][32][32];   // (mean, rstd) per (branch,b,group)

__constant__ float c_cos8[8] = {
    1.f, 0.70710678118654752f, 0.f, -0.70710678118654752f,
   -1.f, -0.70710678118654752f, 0.f, 0.70710678118654752f};

// K1: silu(t) @ adaW^T + b -> symmetrized spectrum -> spatial kernel -> M
__global__ void __launch_bounds__(256) k_prep(
    const float* __restrict__ t,
    const float* __restrict__ wmsa, const float* __restrict__ bmsa,
    const float* __restrict__ wmlp, const float* __restrict__ bmlp)
{
    int b = blockIdx.x, tid = threadIdx.x;
    __shared__ float st[640];
    __shared__ float s[2][40];
    __shared__ float seff[2][64];
    __shared__ float ker[2][64];

    for (int i = tid; i < 640; i += 256) {
        float v = t[b * 640 + i];
        st[i] = v / (1.f + __expf(-v));
    }
    __syncthreads();
    if (tid < 80) {
        int br = tid / 40, f = tid % 40;
        const float* w  = br ? wmlp : wmsa;
        const float* bb = br ? bmlp : bmsa;
        float acc = bb[f];
        for (int e = 0; e < 640; e++) acc = fmaf(st[e], w[f * 640 + e], acc);
        s[br][f] = acc;
    }
    __syncthreads();
    if (tid < 128) {
        int br = tid >> 6, i = tid & 63, k1 = i >> 3, k2 = i & 7;
        float v;
        if (k2 == 0 || k2 == 4)
            v = 0.5f * (s[br][k1 * 5 + k2] + s[br][((8 - k1) & 7) * 5 + k2]);
        else if (k2 < 4) v = s[br][k1 * 5 + k2];
        else             v = s[br][((8 - k1) & 7) * 5 + (8 - k2)];
        seff[br][i] = v;
    }
    __syncthreads();
    if (tid < 128) {
        int br = tid >> 6, i = tid & 63, d1 = i >> 3, d2 = i & 7;
        float acc = 0.f;
        #pragma unroll
        for (int k = 0; k < 64; k++)
            acc = fmaf(seff[br][k], c_cos8[((k >> 3) * d1 + (k & 7) * d2) & 7], acc);
        ker[br][i] = acc * (1.f / 64.f);
    }
    __syncthreads();
    for (int idx = tid; idx < 8192; idx += 256) {
        int br = idx >> 12, j = idx & 4095;
        int in = j >> 6, out = j & 63;
        g_M[br][b][j] = ker[br][(((out >> 3) - (in >> 3)) & 7) * 8 +
                               (((out & 7) - (in & 7)) & 7)];
    }
}

// K2: GroupNorm stats per (b, group): 6 ch * 4096 px
__global__ void __launch_bounds__(256) k_gnstats(const float* __restrict__ x, int gi)
{
    int g = blockIdx.x, b = blockIdx.y;
    const float* p = x + ((size_t)b * 192 + g * 6) * 4096;
    float s = 0.f, s2 = 0.f;
    for (int i = threadIdx.x; i < 24576; i += 256) {
        float v = p[i]; s += v; s2 = fmaf(v, v, s2);
    }
    #pragma unroll
    for (int o = 16; o; o >>= 1) {
        s += __shfl_xor_sync(~0u, s, o); s2 += __shfl_xor_sync(~0u, s2, o);
    }
    __shared__ float sh[2][8];
    int wid = threadIdx.x >> 5;
    if (!(threadIdx.x & 31)) { sh[0][wid] = s; sh[1][wid] = s2; }
    __syncthreads();
    if (threadIdx.x < 32) {
        s  = (threadIdx.x < 8) ? sh[0][threadIdx.x] : 0.f;
        s2 = (threadIdx.x < 8) ? sh[1][threadIdx.x] : 0.f;
        #pragma unroll
        for (int o = 4; o; o >>= 1) {
            s += __shfl_xor_sync(~0u, s, o); s2 += __shfl_xor_sync(~0u, s2, o);
        }
        if (!threadIdx.x) {
            float m = s * (1.f / 24576.f);
            float var = s2 * (1.f / 24576.f) - m * m;
            g_gn[gi][b][g] = make_float2(m, rsqrtf(var + 1e-5f));
        }
    }
}

// K3: GN apply + adafm (64x64 patch GEMM) + scatter
// MODE 0: roll(-4,-4) + window partition -> g_tok ; MODE 1: token-major -> g_tok
template <int MODE>
__global__ void __launch_bounds__(256) k_adafm(
    const float* __restrict__ src,
    const float* __restrict__ gw, const float* __restrict__ gbv)
{
    extern __shared__ float sm[];
    float* Xs = sm;               // 64 x 196
    float* Ms = sm + 64 * 196;    // 4096
    float* ga = Ms + 4096;        // 192
    float* gb = ga + 192;         // 192
    int patch = blockIdx.x, b = blockIdx.y;
    int py = patch >> 3, px = patch & 7, tid = threadIdx.x;

    if (tid < 192) {
        float2 st = g_gn[MODE][b][tid / 6];
        float a = st.y * gw[tid];
        ga[tid] = a; gb[tid] = gbv[tid] - st.x * a;
    }
    for (int i = tid; i < 4096; i += 256) Ms[i] = g_M[MODE][b][i];
    __syncthreads();

    int u = tid >> 5, cl = tid & 31;
    const float* sb = src + ((size_t)b * 192) * 4096 + (py * 8 + u) * 64 + px * 8;
    #pragma unroll
    for (int cb = 0; cb < 6; cb++) {
        int c = cb * 32 + cl;
        const float* pr = sb + (size_t)c * 4096;
        float4 v0 = *(const float4*)pr;
        float4 v1 = *(const float4*)(pr + 4);
        float a = ga[c], o = gb[c];
        float vv[8] = {v0.x, v0.y, v0.z, v0.w, v1.x, v1.y, v1.z, v1.w};
        #pragma unroll
        for (int j = 0; j < 8; j++)
            Xs[(u * 8 + j) * 196 + c] = fmaf(vv[j], a, o);
    }
    __syncthreads();

    int p = tid & 63, cg = tid >> 6;
    float4 acc[12];
    #pragma unroll
    for (int j = 0; j < 12; j++) acc[j] = make_float4(0.f, 0.f, 0.f, 0.f);
    for (int uu = 0; uu < 64; uu++) {
        float m = Ms[uu * 64 + p];
        const float4* xr = (const float4*)(Xs + uu * 196) + cg * 12;
        #pragma unroll
        for (int j = 0; j < 12; j++) {
            float4 xv = xr[j];
            acc[j].x = fmaf(m, xv.x, acc[j].x);
            acc[j].y = fmaf(m, xv.y, acc[j].y);
            acc[j].z = fmaf(m, xv.z, acc[j].z);
            acc[j].w = fmaf(m, xv.w, acc[j].w);
        }
    }
    int hh = py * 8 + (p >> 3), ww = px * 8 + (p & 7);
    float4* op;
    if (MODE == 0) {
        int hh2 = (hh + 60) & 63, ww2 = (ww + 60) & 63;
        int win = ((hh2 >> 3) << 3) | (ww2 >> 3);
        int nn  = ((hh2 & 7) << 3) | (ww2 & 7);
        op = (float4*)(g_tok + (((size_t)(b * 64 + win) * 64 + nn) * 192) + cg * 48);
    } else {
        op = (float4*)(g_tok + (((size_t)b * 4096 + hh * 64 + ww) * 192) + cg * 48);
    }
    #pragma unroll
    for (int j = 0; j < 12; j++) op[j] = acc[j];
}

// K4: SGEMM C[m][n] = sum_k A[m][k] * W[n][k]  (+ epilogues)
// EPI 0: +bias store | 1: +bias GELU | 2: +bias window-reverse+roll+res | 3: +bias chan-major+res
template <int EPI>
__global__ void __launch_bounds__(256) k_gemm(
    const float* __restrict__ A, const float* __restrict__ W,
    const float* __restrict__ bias, float* __restrict__ C,
    int K, int N, const float* __restrict__ res)
{
    __shared__ float As[16 * 132];
    __shared__ float Bs[16 * 68];
    int m0 = blockIdx.y * 128, n0 = blockIdx.x * 64;
    int tid = threadIdx.x, tx = tid & 15, ty = tid >> 4;
    float acc[8][4];
    #pragma unroll
    for (int i = 0; i < 8; i++)
        #pragma unroll
        for (int j = 0; j < 4; j++) acc[i][j] = 0.f;

    const float* Ab = A + (size_t)m0 * K;
    const float* Wb = W + (size_t)n0 * K;
    for (int k0 = 0; k0 < K; k0 += 16) {
        #pragma unroll
        for (int r = 0; r < 2; r++) {
            int e = tid + r * 256, row = e >> 2, kq = e & 3;
            float4 v = *(const float4*)(Ab + (size_t)row * K + k0 + kq * 4);
            As[(kq * 4 + 0) * 132 + row] = v.x;
            As[(kq * 4 + 1) * 132 + row] = v.y;
            As[(kq * 4 + 2) * 132 + row] = v.z;
            As[(kq * 4 + 3) * 132 + row] = v.w;
        }
        {
            int row = tid >> 2, kq = tid & 3;
            float4 v = *(const float4*)(Wb + (size_t)row * K + k0 + kq * 4);
            Bs[(kq * 4 + 0) * 68 + row] = v.x;
            Bs[(kq * 4 + 1) * 68 + row] = v.y;
            Bs[(kq * 4 + 2) * 68 + row] = v.z;
            Bs[(kq * 4 + 3) * 68 + row] = v.w;
        }
        __syncthreads();
        #pragma unroll
        for (int k = 0; k < 16; k++) {
            float4 a0 = *(const float4*)(&As[k * 132 + ty * 8]);
            float4 a1 = *(const float4*)(&As[k * 132 + ty * 8 + 4]);
            float4 bv = *(const float4*)(&Bs[k * 68 + tx * 4]);
            float a[8] = {a0.x, a0.y, a0.z, a0.w, a1.x, a1.y, a1.z, a1.w};
            float bb[4] = {bv.x, bv.y, bv.z, bv.w};
            #pragma unroll
            for (int i = 0; i < 8; i++)
                #pragma unroll
                for (int j = 0; j < 4; j++)
                    acc[i][j] = fmaf(a[i], bb[j], acc[i][j]);
        }
        __syncthreads();
    }

    float bl[4];
    #pragma unroll
    for (int j = 0; j < 4; j++) bl[j] = bias[n0 + tx * 4 + j];
    #pragma unroll
    for (int i = 0; i < 8; i++) {
        int m = m0 + ty * 8 + i;
        if (EPI == 0) {
            float4 v = make_float4(acc[i][0] + bl[0], acc[i][1] + bl[1],
                                   acc[i][2] + bl[2], acc[i][3] + bl[3]);
            *(float4*)(C + (size_t)m * N + n0 + tx * 4) = v;
        } else if (EPI == 1) {
            float t0 = acc[i][0] + bl[0], t1 = acc[i][1] + bl[1];
            float t2 = acc[i][2] + bl[2], t3 = acc[i][3] + bl[3];
            float4 v;
            v.x = 0.5f * t0 * (1.f + erff(t0 * 0.70710678118654752f));
            v.y = 0.5f * t1 * (1.f + erff(t1 * 0.70710678118654752f));
            v.z = 0.5f * t2 * (1.f + erff(t2 * 0.70710678118654752f));
            v.w = 0.5f * t3 * (1.f + erff(t3 * 0.70710678118654752f));
            *(float4*)(C + (size_t)m * N + n0 + tx * 4) = v;
        } else if (EPI == 2) {
            int b = m >> 12, win = (m >> 6) & 63, nn = m & 63;
            int hh = ((((win >> 3) << 3) + (nn >> 3)) + 4) & 63;
            int ww = ((((win & 7) << 3) + (nn & 7)) + 4) & 63;
            size_t base = ((size_t)b * 192) * 4096 + hh * 64 + ww;
            #pragma unroll
            for (int j = 0; j < 4; j++) {
                size_t idx = base + (size_t)(n0 + tx * 4 + j) * 4096;
                C[idx] = res[idx] + acc[i][j] + bl[j];
            }
        } else {
            int b = m >> 12, pix = m & 4095;
            #pragma unroll
            for (int j = 0; j < 4; j++) {
                size_t idx = ((size_t)(b * 192 + n0 + tx * 4 + j)) * 4096 + pix;
                C[idx] = res[idx] + acc[i][j] + bl[j];
            }
        }
    }
}

// K5: fused window attention, one block per (window, head), thread = query row
__global__ void __launch_bounds__(64) k_attn(
    const float* __restrict__ qkv, const float* __restrict__ rpb,
    float* __restrict__ aout)
{
    int w = blockIdx.x, head = blockIdx.y, n = threadIdx.x;
    __shared__ float Ks[64 * 32], Vs[64 * 32], Pr[64 * 64], Br[225];
    __shared__ int Cat[64];

    const float* base = qkv + (size_t)w * 64 * 576 + head * 32;
    {
        const float4* kp = (const float4*)(base + (size_t)n * 576 + 192);
        const float4* vp = (const float4*)(base + (size_t)n * 576 + 384);
        float4* kd = (float4*)(Ks + n * 32);
        float4* vd = (float4*)(Vs + n * 32);
        #pragma unroll
        for (int i = 0; i < 8; i++) { kd[i] = kp[i]; vd[i] = vp[i]; }
    }
    for (int i = n; i < 225; i += 64) Br[i] = rpb[i * 6 + head];
    {
        int win = w & 63;
        int hh2 = ((win >> 3) << 3) + (n >> 3);
        int ww2 = ((win & 7) << 3) + (n & 7);
        int ch = hh2 < 56 ? 0 : (hh2 < 60 ? 1 : 2);
        int cw = ww2 < 56 ? 0 : (ww2 < 60 ? 1 : 2);
        Cat[n] = ch * 3 + cw;
    }
    float q[32];
    {
        const float4* qp = (const float4*)(base + (size_t)n * 576);
        #pragma unroll
        for (int i = 0; i < 8; i++) {
            float4 v = qp[i];
            q[i * 4 + 0] = v.x * SCALE_Q; q[i * 4 + 1] = v.y * SCALE_Q;
            q[i * 4 + 2] = v.z * SCALE_Q; q[i * 4 + 3] = v.w * SCALE_Q;
        }
    }
    __syncthreads();

    int rn = n >> 3, cn = n & 7, mycat = Cat[n];
    float mx = -1e30f;
    for (int m = 0; m < 64; m++) {
        float d = 0.f;
        const float* kr = Ks + m * 32;
        #pragma unroll
        for (int i = 0; i < 32; i++) d = fmaf(q[i], kr[i], d);
        d += Br[(rn - (m >> 3) + 7) * 15 + (cn - (m & 7) + 7)];
        if (Cat[m] != mycat) d -= 100.f;
        Pr[m * 64 + n] = d;
        mx = fmaxf(mx, d);
    }
    float sum = 0.f;
    for (int m = 0; m < 64; m++) {
        float e = __expf(Pr[m * 64 + n] - mx);
        Pr[m * 64 + n] = e;
        sum += e;
    }
    float inv = 1.f / sum;
    float acc[32];
    #pragma unroll
    for (int i = 0; i < 32; i++) acc[i] = 0.f;
    for (int m = 0; m < 64; m++) {
        float p = Pr[m * 64 + n];
        const float* vr = Vs + m * 32;
        #pragma unroll
        for (int i = 0; i < 32; i++) acc[i] = fmaf(p, vr[i], acc[i]);
    }
    float* op = aout + ((size_t)w * 64 + n) * 192 + head * 32;
    #pragma unroll
    for (int i = 0; i < 8; i++)
        *(float4*)(op + i * 4) = make_float4(acc[i*4]*inv, acc[i*4+1]*inv,
                                             acc[i*4+2]*inv, acc[i*4+3]*inv);
}

extern "C" void kernel_launch(void* const* d_in, const int* in_sizes, int n_in,
                              void* d_out, int out_size)
{
    const float* x    = (const float*)d_in[0];
    const float* t    = (const float*)d_in[1];
    const float* n1w  = (const float*)d_in[2];
    const float* n1b  = (const float*)d_in[3];
    const float* qkvw = (const float*)d_in[4];
    const float* qkvb = (const float*)d_in[5];
    const float* rpb  = (const float*)d_in[6];
    const float* pw   = (const float*)d_in[7];
    const float* pb   = (const float*)d_in[8];
    const float* n2w  = (const float*)d_in[9];
    const float* n2b  = (const float*)d_in[10];
    const float* f1w  = (const float*)d_in[11];
    const float* f1b  = (const float*)d_in[12];
    const float* f2w  = (const float*)d_in[13];
    const float* f2b  = (const float*)d_in[14];
    const float* amw  = (const float*)d_in[15];
    const float* amb  = (const float*)d_in[16];
    const float* alw  = (const float*)d_in[17];
    const float* alb  = (const float*)d_in[18];
    float* out = (float*)d_out;

    float *tok, *big, *x2;
    cudaGetSymbolAddress((void**)&tok, g_tok);
    cudaGetSymbolAddress((void**)&big, g_big);
    cudaGetSymbolAddress((void**)&x2,  g_x2v);

    const int ADAFM_SMEM = (64 * 196 + 4096 + 384) * 4;
    static int attr_done = 0;
    if (!attr_done) {
        cudaFuncSetAttribute(k_adafm<0>, cudaFuncAttributeMaxDynamicSharedMemorySize, ADAFM_SMEM);
        cudaFuncSetAttribute(k_adafm<1>, cudaFuncAttributeMaxDynamicSharedMemorySize, ADAFM_SMEM);
        attr_done = 1;
    }

    // prep: conv matrices for both branches
    k_prep<<<32, 256>>>(t, amw, amb, alw, alb);
    // GN1 stats on x
    k_gnstats<<<dim3(32, 32), 256>>>(x, 0);
    // GN1 + adafm + shift + window partition -> g_tok (xw)
    k_adafm<0><<<dim3(64, 32), 256, ADAFM_SMEM>>>(x, n1w, n1b);
    // qkv: (131072 x 192) @ (576 x 192)^T -> g_big
    k_gemm<0><<<dim3(9, 1024), 256>>>(tok, qkvw, qkvb, big, 192, 576, nullptr);
    // attention -> g_tok
    k_attn<<<dim3(2048, 6), 64>>>(big, rpb, tok);
    // proj + window reverse + roll + residual -> g_x2v
    k_gemm<2><<<dim3(3, 1024), 256>>>(tok, pw, pb, x2, 192, 192, x);
    // GN2 stats on x2
    k_gnstats<<<dim3(32, 32), 256>>>(x2, 1);
    // GN2 + adafm -> g_tok (token-major h2)
    k_adafm<1><<<dim3(64, 32), 256, ADAFM_SMEM>>>(x2, n2w, n2b);
    // fc1 + GELU: (131072 x 192) @ (768 x 192)^T -> g_big
    k_gemm<1><<<dim3(12, 1024), 256>>>(tok, f1w, f1b, big, 192, 768, nullptr);
    // fc2 + residual scatter: (131072 x 768) @ (192 x 768)^T -> out
    k_gemm<3><<<dim3(3, 1024), 256>>>(big, f2w, f2b, out, 768, 192, x2);
}

// round 3
// speedup vs baseline: 1.3595x; 1.3595x over previous
#include <cuda_runtime.h>
#include <cuda_bf16.h>
#include <math.h>

#define SCALE_Q 0.17677669529663687f

// scratch (device globals, aliased across phases)
__device__ float g_tok[25165824];    // xw -> attn_out -> h2   (131072 x 192)
__device__ float g_big[100663296];   // qkv -> hid             (131072 x 576/768)
__device__ float g_x2v[25165824];    // x after attn residual  (B,C,H,W)
__device__ float g_M[2][32][4096];   // per-batch 64x64 patch conv matrices
__device__ float2 g_gn[2][32][32];   // (mean, rstd) per (branch,b,group)

__constant__ float c_cos8[8] = {
    1.f, 0.70710678118654752f, 0.f, -0.70710678118654752f,
   -1.f, -0.70710678118654752f, 0.f, 0.70710678118654752f};

// ---------------- K1: adaFM spectra -> per-batch 64x64 conv matrices --------
__global__ void __launch_bounds__(256) k_prep(
    const float* __restrict__ t,
    const float* __restrict__ wmsa, const float* __restrict__ bmsa,
    const float* __restrict__ wmlp, const float* __restrict__ bmlp)
{
    int b = blockIdx.x, tid = threadIdx.x;
    __shared__ float st[640];
    __shared__ float s[2][40];
    __shared__ float seff[2][64];
    __shared__ float ker[2][64];

    for (int i = tid; i < 640; i += 256) {
        float v = t[b * 640 + i];
        st[i] = v / (1.f + __expf(-v));
    }
    __syncthreads();
    if (tid < 80) {
        int br = tid / 40, f = tid % 40;
        const float* w  = br ? wmlp : wmsa;
        const float* bb = br ? bmlp : bmsa;
        float acc = bb[f];
        for (int e = 0; e < 640; e++) acc = fmaf(st[e], w[f * 640 + e], acc);
        s[br][f] = acc;
    }
    __syncthreads();
    if (tid < 128) {
        int br = tid >> 6, i = tid & 63, k1 = i >> 3, k2 = i & 7;
        float v;
        if (k2 == 0 || k2 == 4)
            v = 0.5f * (s[br][k1 * 5 + k2] + s[br][((8 - k1) & 7) * 5 + k2]);
        else if (k2 < 4) v = s[br][k1 * 5 + k2];
        else             v = s[br][((8 - k1) & 7) * 5 + (8 - k2)];
        seff[br][i] = v;
    }
    __syncthreads();
    if (tid < 128) {
        int br = tid >> 6, i = tid & 63, d1 = i >> 3, d2 = i & 7;
        float acc = 0.f;
        #pragma unroll
        for (int k = 0; k < 64; k++)
            acc = fmaf(seff[br][k], c_cos8[((k >> 3) * d1 + (k & 7) * d2) & 7], acc);
        ker[br][i] = acc * (1.f / 64.f);
    }
    __syncthreads();
    for (int idx = tid; idx < 8192; idx += 256) {
        int br = idx >> 12, j = idx & 4095;
        int in = j >> 6, out = j & 63;
        g_M[br][b][j] = ker[br][(((out >> 3) - (in >> 3)) & 7) * 8 +
                               (((out & 7) - (in & 7)) & 7)];
    }
}

// ---------------- K2: GroupNorm stats ---------------------------------------
__global__ void __launch_bounds__(256) k_gnstats(const float* __restrict__ x, int gi)
{
    int g = blockIdx.x, b = blockIdx.y;
    const float* p = x + ((size_t)b * 192 + g * 6) * 4096;
    float s = 0.f, s2 = 0.f;
    for (int i = threadIdx.x; i < 24576; i += 256) {
        float v = p[i]; s += v; s2 = fmaf(v, v, s2);
    }
    #pragma unroll
    for (int o = 16; o; o >>= 1) {
        s += __shfl_xor_sync(~0u, s, o); s2 += __shfl_xor_sync(~0u, s2, o);
    }
    __shared__ float sh[2][8];
    int wid = threadIdx.x >> 5;
    if (!(threadIdx.x & 31)) { sh[0][wid] = s; sh[1][wid] = s2; }
    __syncthreads();
    if (threadIdx.x < 32) {
        s  = (threadIdx.x < 8) ? sh[0][threadIdx.x] : 0.f;
        s2 = (threadIdx.x < 8) ? sh[1][threadIdx.x] : 0.f;
        #pragma unroll
        for (int o = 4; o; o >>= 1) {
            s += __shfl_xor_sync(~0u, s, o); s2 += __shfl_xor_sync(~0u, s2, o);
        }
        if (!threadIdx.x) {
            float m = s * (1.f / 24576.f);
            float var = s2 * (1.f / 24576.f) - m * m;
            g_gn[gi][b][g] = make_float2(m, rsqrtf(var + 1e-5f));
        }
    }
}

// ---------------- K3: GN apply + adafm patch GEMM + scatter -----------------
template <int MODE>
__global__ void __launch_bounds__(256) k_adafm(
    const float* __restrict__ src,
    const float* __restrict__ gw, const float* __restrict__ gbv)
{
    extern __shared__ float sm[];
    float* Xs = sm;               // 64 x 196
    float* Ms = sm + 64 * 196;    // 4096
    float* ga = Ms + 4096;        // 192
    float* gb = ga + 192;         // 192
    int patch = blockIdx.x, b = blockIdx.y;
    int py = patch >> 3, px = patch & 7, tid = threadIdx.x;

    if (tid < 192) {
        float2 st = g_gn[MODE][b][tid / 6];
        float a = st.y * gw[tid];
        ga[tid] = a; gb[tid] = gbv[tid] - st.x * a;
    }
    for (int i = tid; i < 4096; i += 256) Ms[i] = g_M[MODE][b][i];
    __syncthreads();

    int u = tid >> 5, cl = tid & 31;
    const float* sb = src + ((size_t)b * 192) * 4096 + (py * 8 + u) * 64 + px * 8;
    #pragma unroll
    for (int cb = 0; cb < 6; cb++) {
        int c = cb * 32 + cl;
        const float* pr = sb + (size_t)c * 4096;
        float4 v0 = *(const float4*)pr;
        float4 v1 = *(const float4*)(pr + 4);
        float a = ga[c], o = gb[c];
        float vv[8] = {v0.x, v0.y, v0.z, v0.w, v1.x, v1.y, v1.z, v1.w};
        #pragma unroll
        for (int j = 0; j < 8; j++)
            Xs[(u * 8 + j) * 196 + c] = fmaf(vv[j], a, o);
    }
    __syncthreads();

    int p = tid & 63, cg = tid >> 6;
    float4 acc[12];
    #pragma unroll
    for (int j = 0; j < 12; j++) acc[j] = make_float4(0.f, 0.f, 0.f, 0.f);
    for (int uu = 0; uu < 64; uu++) {
        float m = Ms[uu * 64 + p];
        const float4* xr = (const float4*)(Xs + uu * 196) + cg * 12;
        #pragma unroll
        for (int j = 0; j < 12; j++) {
            float4 xv = xr[j];
            acc[j].x = fmaf(m, xv.x, acc[j].x);
            acc[j].y = fmaf(m, xv.y, acc[j].y);
            acc[j].z = fmaf(m, xv.z, acc[j].z);
            acc[j].w = fmaf(m, xv.w, acc[j].w);
        }
    }
    int hh = py * 8 + (p >> 3), ww = px * 8 + (p & 7);
    float4* op;
    if (MODE == 0) {
        int hh2 = (hh + 60) & 63, ww2 = (ww + 60) & 63;
        int win = ((hh2 >> 3) << 3) | (ww2 >> 3);
        int nn  = ((hh2 & 7) << 3) | (ww2 & 7);
        op = (float4*)(g_tok + (((size_t)(b * 64 + win) * 64 + nn) * 192) + cg * 48);
    } else {
        op = (float4*)(g_tok + (((size_t)b * 4096 + hh * 64 + ww) * 192) + cg * 48);
    }
    #pragma unroll
    for (int j = 0; j < 12; j++) op[j] = acc[j];
}

// ---------------- K4: tensor-core GEMM (bf16 2-way split, fp32 acc) ---------
// C[m][n] = sum_k A[m][k] * W[n][k], block tile 128x64, warp tile 32x32.
// EPI 0: +bias | 1: +bias GELU | 2: +bias win-reverse+roll+res | 3: +bias chan-major+res
__device__ __forceinline__ void cvt2(float x, float y, unsigned& hi, unsigned& lo)
{
    __nv_bfloat16 hx = __float2bfloat16(x), hy = __float2bfloat16(y);
    __nv_bfloat16 lx = __float2bfloat16(x - __bfloat162float(hx));
    __nv_bfloat16 ly = __float2bfloat16(y - __bfloat162float(hy));
    hi = (unsigned)__bfloat16_as_ushort(hx) | ((unsigned)__bfloat16_as_ushort(hy) << 16);
    lo = (unsigned)__bfloat16_as_ushort(lx) | ((unsigned)__bfloat16_as_ushort(ly) << 16);
}

__device__ __forceinline__ void mma16816(float* c, const unsigned* a, const unsigned* b)
{
    asm volatile(
        "mma.sync.aligned.m16n8k16.row.col.f32.bf16.bf16.f32 "
        "{%0,%1,%2,%3}, {%4,%5,%6,%7}, {%8,%9}, {%0,%1,%2,%3};"
        : "+f"(c[0]), "+f"(c[1]), "+f"(c[2]), "+f"(c[3])
        : "r"(a[0]), "r"(a[1]), "r"(a[2]), "r"(a[3]), "r"(b[0]), "r"(b[1]));
}

template <int EPI>
__global__ void __launch_bounds__(256) k_gemm_tc(
    const float* __restrict__ A, const float* __restrict__ W,
    const float* __restrict__ bias, float* __restrict__ C,
    int K, int N, const float* __restrict__ res)
{
    // smem tiles as u32 (pair of bf16), k-stride 9 u32 (16 k + pad)
    __shared__ unsigned Ash[128 * 9], Asl[128 * 9];
    __shared__ unsigned Bsh[64 * 9],  Bsl[64 * 9];

    int m0 = blockIdx.y * 128, n0 = blockIdx.x * 64;
    int tid = threadIdx.x, lane = tid & 31, wid = tid >> 5;
    int wm = (wid & 3) * 32, wn = (wid >> 2) * 32;
    int g = lane >> 2, tg = lane & 3;

    float c[2][4][4];
    #pragma unroll
    for (int mt = 0; mt < 2; mt++)
        #pragma unroll
        for (int nt = 0; nt < 4; nt++)
            #pragma unroll
            for (int i = 0; i < 4; i++) c[mt][nt][i] = 0.f;

    const float* Ab = A + (size_t)m0 * K;
    const float* Wb = W + (size_t)n0 * K;

    for (int k0 = 0; k0 < K; k0 += 16) {
        // fill A tile: 128 rows x 16 k, 2 float4 per thread
        #pragma unroll
        for (int r = 0; r < 2; r++) {
            int e = tid * 2 + r, row = e >> 2, kq = e & 3;
            float4 v = *(const float4*)(Ab + (size_t)row * K + k0 + kq * 4);
            unsigned h0, l0, h1, l1;
            cvt2(v.x, v.y, h0, l0);
            cvt2(v.z, v.w, h1, l1);
            int o = row * 9 + kq * 2;
            Ash[o] = h0; Ash[o + 1] = h1;
            Asl[o] = l0; Asl[o + 1] = l1;
        }
        // fill B tile: 64 rows x 16 k, 1 float4 per thread
        {
            int row = tid >> 2, kq = tid & 3;
            float4 v = *(const float4*)(Wb + (size_t)row * K + k0 + kq * 4);
            unsigned h0, l0, h1, l1;
            cvt2(v.x, v.y, h0, l0);
            cvt2(v.z, v.w, h1, l1);
            int o = row * 9 + kq * 2;
            Bsh[o] = h0; Bsh[o + 1] = h1;
            Bsl[o] = l0; Bsl[o + 1] = l1;
        }
        __syncthreads();

        unsigned ah[2][4], al[2][4], bh[4][2], bl[4][2];
        #pragma unroll
        for (int mt = 0; mt < 2; mt++) {
            int r = wm + mt * 16 + g;
            ah[mt][0] = Ash[r * 9 + tg];       al[mt][0] = Asl[r * 9 + tg];
            ah[mt][1] = Ash[(r + 8) * 9 + tg]; al[mt][1] = Asl[(r + 8) * 9 + tg];
            ah[mt][2] = Ash[r * 9 + tg + 4];   al[mt][2] = Asl[r * 9 + tg + 4];
            ah[mt][3] = Ash[(r + 8) * 9 + tg + 4]; al[mt][3] = Asl[(r + 8) * 9 + tg + 4];
        }
        #pragma unroll
        for (int nt = 0; nt < 4; nt++) {
            int r = wn + nt * 8 + g;
            bh[nt][0] = Bsh[r * 9 + tg];     bl[nt][0] = Bsl[r * 9 + tg];
            bh[nt][1] = Bsh[r * 9 + tg + 4]; bl[nt][1] = Bsl[r * 9 + tg + 4];
        }
        #pragma unroll
        for (int mt = 0; mt < 2; mt++)
            #pragma unroll
            for (int nt = 0; nt < 4; nt++) {
                mma16816(c[mt][nt], ah[mt], bh[nt]);   // hi*hi
                mma16816(c[mt][nt], ah[mt], bl[nt]);   // hi*lo
                mma16816(c[mt][nt], al[mt], bh[nt]);   // lo*hi
            }
        __syncthreads();
    }

    // epilogue: element (mt,nt,i): row = m0+wm+mt*16+g+8*(i>>1), col = n0+wn+nt*8+tg*2+(i&1)
    #pragma unroll
    for (int nt = 0; nt < 4; nt++) {
        int cb = n0 + wn + nt * 8 + tg * 2;
        float2 bv = *(const float2*)(bias + cb);
        #pragma unroll
        for (int mt = 0; mt < 2; mt++) {
            #pragma unroll
            for (int h = 0; h < 2; h++) {
                int m = m0 + wm + mt * 16 + g + h * 8;
                float v0 = c[mt][nt][h * 2 + 0] + bv.x;
                float v1 = c[mt][nt][h * 2 + 1] + bv.y;
                if (EPI == 0) {
                    *(float2*)(C + (size_t)m * N + cb) = make_float2(v0, v1);
                } else if (EPI == 1) {
                    float g0 = 0.5f * v0 * (1.f + erff(v0 * 0.70710678118654752f));
                    float g1 = 0.5f * v1 * (1.f + erff(v1 * 0.70710678118654752f));
                    *(float2*)(C + (size_t)m * N + cb) = make_float2(g0, g1);
                } else if (EPI == 2) {
                    int b = m >> 12, win = (m >> 6) & 63, nn = m & 63;
                    int hh = ((((win >> 3) << 3) + (nn >> 3)) + 4) & 63;
                    int ww = ((((win & 7) << 3) + (nn & 7)) + 4) & 63;
                    size_t base = ((size_t)b * 192) * 4096 + hh * 64 + ww;
                    size_t i0 = base + (size_t)cb * 4096;
                    size_t i1 = base + (size_t)(cb + 1) * 4096;
                    C[i0] = res[i0] + v0;
                    C[i1] = res[i1] + v1;
                } else {
                    int b = m >> 12, pix = m & 4095;
                    size_t i0 = ((size_t)(b * 192 + cb)) * 4096 + pix;
                    size_t i1 = i0 + 4096;
                    C[i0] = res[i0] + v0;
                    C[i1] = res[i1] + v1;
                }
            }
        }
    }
}

// ---------------- K5: fused window attention ---------------------------------
__global__ void __launch_bounds__(64) k_attn(
    const float* __restrict__ qkv, const float* __restrict__ rpb,
    float* __restrict__ aout)
{
    int w = blockIdx.x, head = blockIdx.y, n = threadIdx.x;
    __shared__ float Ks[64 * 32], Vs[64 * 32], Pr[64 * 64], Br[225];
    __shared__ int Cat[64];

    const float* base = qkv + (size_t)w * 64 * 576 + head * 32;
    {
        const float4* kp = (const float4*)(base + (size_t)n * 576 + 192);
        const float4* vp = (const float4*)(base + (size_t)n * 576 + 384);
        float4* kd = (float4*)(Ks + n * 32);
        float4* vd = (float4*)(Vs + n * 32);
        #pragma unroll
        for (int i = 0; i < 8; i++) { kd[i] = kp[i]; vd[i] = vp[i]; }
    }
    for (int i = n; i < 225; i += 64) Br[i] = rpb[i * 6 + head];
    {
        int win = w & 63;
        int hh2 = ((win >> 3) << 3) + (n >> 3);
        int ww2 = ((win & 7) << 3) + (n & 7);
        int ch = hh2 < 56 ? 0 : (hh2 < 60 ? 1 : 2);
        int cw = ww2 < 56 ? 0 : (ww2 < 60 ? 1 : 2);
        Cat[n] = ch * 3 + cw;
    }
    float q[32];
    {
        const float4* qp = (const float4*)(base + (size_t)n * 576);
        #pragma unroll
        for (int i = 0; i < 8; i++) {
            float4 v = qp[i];
            q[i * 4 + 0] = v.x * SCALE_Q; q[i * 4 + 1] = v.y * SCALE_Q;
            q[i * 4 + 2] = v.z * SCALE_Q; q[i * 4 + 3] = v.w * SCALE_Q;
        }
    }
    __syncthreads();

    int rn = n >> 3, cn = n & 7, mycat = Cat[n];
    float mx = -1e30f;
    for (int m = 0; m < 64; m++) {
        float d = 0.f;
        const float* kr = Ks + m * 32;
        #pragma unroll
        for (int i = 0; i < 32; i++) d = fmaf(q[i], kr[i], d);
        d += Br[(rn - (m >> 3) + 7) * 15 + (cn - (m & 7) + 7)];
        if (Cat[m] != mycat) d -= 100.f;
        Pr[m * 64 + n] = d;
        mx = fmaxf(mx, d);
    }
    float sum = 0.f;
    for (int m = 0; m < 64; m++) {
        float e = __expf(Pr[m * 64 + n] - mx);
        Pr[m * 64 + n] = e;
        sum += e;
    }
    float inv = 1.f / sum;
    float acc[32];
    #pragma unroll
    for (int i = 0; i < 32; i++) acc[i] = 0.f;
    for (int m = 0; m < 64; m++) {
        float p = Pr[m * 64 + n];
        const float* vr = Vs + m * 32;
        #pragma unroll
        for (int i = 0; i < 32; i++) acc[i] = fmaf(p, vr[i], acc[i]);
    }
    float* op = aout + ((size_t)w * 64 + n) * 192 + head * 32;
    #pragma unroll
    for (int i = 0; i < 8; i++)
        *(float4*)(op + i * 4) = make_float4(acc[i*4]*inv, acc[i*4+1]*inv,
                                             acc[i*4+2]*inv, acc[i*4+3]*inv);
}

extern "C" void kernel_launch(void* const* d_in, const int* in_sizes, int n_in,
                              void* d_out, int out_size)
{
    const float* x    = (const float*)d_in[0];
    const float* t    = (const float*)d_in[1];
    const float* n1w  = (const float*)d_in[2];
    const float* n1b  = (const float*)d_in[3];
    const float* qkvw = (const float*)d_in[4];
    const float* qkvb = (const float*)d_in[5];
    const float* rpb  = (const float*)d_in[6];
    const float* pw   = (const float*)d_in[7];
    const float* pb   = (const float*)d_in[8];
    const float* n2w  = (const float*)d_in[9];
    const float* n2b  = (const float*)d_in[10];
    const float* f1w  = (const float*)d_in[11];
    const float* f1b  = (const float*)d_in[12];
    const float* f2w  = (const float*)d_in[13];
    const float* f2b  = (const float*)d_in[14];
    const float* amw  = (const float*)d_in[15];
    const float* amb  = (const float*)d_in[16];
    const float* alw  = (const float*)d_in[17];
    const float* alb  = (const float*)d_in[18];
    float* out = (float*)d_out;

    float *tok, *big, *x2;
    cudaGetSymbolAddress((void**)&tok, g_tok);
    cudaGetSymbolAddress((void**)&big, g_big);
    cudaGetSymbolAddress((void**)&x2,  g_x2v);

    const int ADAFM_SMEM = (64 * 196 + 4096 + 384) * 4;
    static int attr_done = 0;
    if (!attr_done) {
        cudaFuncSetAttribute(k_adafm<0>, cudaFuncAttributeMaxDynamicSharedMemorySize, ADAFM_SMEM);
        cudaFuncSetAttribute(k_adafm<1>, cudaFuncAttributeMaxDynamicSharedMemorySize, ADAFM_SMEM);
        attr_done = 1;
    }

    k_prep<<<32, 256>>>(t, amw, amb, alw, alb);
    k_gnstats<<<dim3(32, 32), 256>>>(x, 0);
    k_adafm<0><<<dim3(64, 32), 256, ADAFM_SMEM>>>(x, n1w, n1b);
    // qkv: (131072 x 192) @ (576 x 192)^T -> g_big
    k_gemm_tc<0><<<dim3(9, 1024), 256>>>(tok, qkvw, qkvb, big, 192, 576, nullptr);
    k_attn<<<dim3(2048, 6), 64>>>(big, rpb, tok);
    // proj + window reverse + roll + residual -> g_x2v
    k_gemm_tc<2><<<dim3(3, 1024), 256>>>(tok, pw, pb, x2, 192, 192, x);
    k_gnstats<<<dim3(32, 32), 256>>>(x2, 1);
    k_adafm<1><<<dim3(64, 32), 256, ADAFM_SMEM>>>(x2, n2w, n2b);
    // fc1 + GELU
    k_gemm_tc<1><<<dim3(12, 1024), 256>>>(tok, f1w, f1b, big, 192, 768, nullptr);
    // fc2 + residual scatter
    k_gemm_tc<3><<<dim3(3, 1024), 256>>>(big, f2w, f2b, out, 768, 192, x2);
}

// round 4
// speedup vs baseline: 1.6334x; 1.2015x over previous
#include <cuda_runtime.h>
#include <cuda_bf16.h>
#include <math.h>

#define SCALE_Q 0.17677669529663687f
#define KSTR 40   // smem row stride in bf16 elems (80B, bank-conflict-free for LDSM)

// ---------------- scratch (device globals) ----------------------------------
__device__ float g_qkv[75497472];            // 131072 x 576 fp32
__device__ float g_x2v[25165824];            // x after attn residual (B,C,H,W)
__device__ __nv_bfloat16 g_ah[25165824];     // activations hi (131072 x 192)
__device__ __nv_bfloat16 g_al[25165824];     // activations lo
__device__ __nv_bfloat16 g_bh[100663296];    // fc1 out hi (131072 x 768)
__device__ __nv_bfloat16 g_bl[100663296];    // fc1 out lo
__device__ __nv_bfloat16 g_wh[442368];       // weights hi (qkv|proj|fc1|fc2)
__device__ __nv_bfloat16 g_wl[442368];       // weights lo
__device__ float g_M[2][32][4096];           // per-batch 64x64 patch conv matrices
__device__ float2 g_gn[2][32][32];           // (mean, rstd)

__constant__ float c_cos8[8] = {
    1.f, 0.70710678118654752f, 0.f, -0.70710678118654752f,
   -1.f, -0.70710678118654752f, 0.f, 0.70710678118654752f};

// ---------------- small helpers ---------------------------------------------
__device__ __forceinline__ unsigned su32(const void* p) {
    return (unsigned)__cvta_generic_to_shared(p);
}
__device__ __forceinline__ void cpasync16(unsigned dst, const void* src) {
    asm volatile("cp.async.ca.shared.global [%0], [%1], 16;" :: "r"(dst), "l"(src) : "memory");
}
__device__ __forceinline__ void cpcommit() {
    asm volatile("cp.async.commit_group;" ::: "memory");
}
template <int W> __device__ __forceinline__ void cpwait() {
    asm volatile("cp.async.wait_group %0;" :: "n"(W) : "memory");
}
__device__ __forceinline__ void ldsm4(unsigned a, unsigned& r0, unsigned& r1,
                                      unsigned& r2, unsigned& r3) {
    asm volatile("ldmatrix.sync.aligned.m8n8.x4.shared.b16 {%0,%1,%2,%3}, [%4];"
                 : "=r"(r0), "=r"(r1), "=r"(r2), "=r"(r3) : "r"(a));
}
__device__ __forceinline__ void mma16816(float* c, const unsigned* a, const unsigned* b) {
    asm volatile(
        "mma.sync.aligned.m16n8k16.row.col.f32.bf16.bf16.f32 "
        "{%0,%1,%2,%3}, {%4,%5,%6,%7}, {%8,%9}, {%0,%1,%2,%3};"
        : "+f"(c[0]), "+f"(c[1]), "+f"(c[2]), "+f"(c[3])
        : "r"(a[0]), "r"(a[1]), "r"(a[2]), "r"(a[3]), "r"(b[0]), "r"(b[1]));
}
__device__ __forceinline__ void splitbf(float v, __nv_bfloat16& h, __nv_bfloat16& l) {
    h = __float2bfloat16(v);
    l = __float2bfloat16(v - __bfloat162float(h));
}

// ---------------- K1: adaFM spectra -> per-batch 64x64 conv matrices --------
__global__ void __launch_bounds__(256) k_prep(
    const float* __restrict__ t,
    const float* __restrict__ wmsa, const float* __restrict__ bmsa,
    const float* __restrict__ wmlp, const float* __restrict__ bmlp)
{
    int b = blockIdx.x, tid = threadIdx.x;
    __shared__ float st[640];
    __shared__ float s[2][40];
    __shared__ float seff[2][64];
    __shared__ float ker[2][64];

    for (int i = tid; i < 640; i += 256) {
        float v = t[b * 640 + i];
        st[i] = v / (1.f + __expf(-v));
    }
    __syncthreads();
    if (tid < 80) {
        int br = tid / 40, f = tid % 40;
        const float* w  = br ? wmlp : wmsa;
        const float* bb = br ? bmlp : bmsa;
        float acc = bb[f];
        for (int e = 0; e < 640; e++) acc = fmaf(st[e], w[f * 640 + e], acc);
        s[br][f] = acc;
    }
    __syncthreads();
    if (tid < 128) {
        int br = tid >> 6, i = tid & 63, k1 = i >> 3, k2 = i & 7;
        float v;
        if (k2 == 0 || k2 == 4)
            v = 0.5f * (s[br][k1 * 5 + k2] + s[br][((8 - k1) & 7) * 5 + k2]);
        else if (k2 < 4) v = s[br][k1 * 5 + k2];
        else             v = s[br][((8 - k1) & 7) * 5 + (8 - k2)];
        seff[br][i] = v;
    }
    __syncthreads();
    if (tid < 128) {
        int br = tid >> 6, i = tid & 63, d1 = i >> 3, d2 = i & 7;
        float acc = 0.f;
        #pragma unroll
        for (int k = 0; k < 64; k++)
            acc = fmaf(seff[br][k], c_cos8[((k >> 3) * d1 + (k & 7) * d2) & 7], acc);
        ker[br][i] = acc * (1.f / 64.f);
    }
    __syncthreads();
    for (int idx = tid; idx < 8192; idx += 256) {
        int br = idx >> 12, j = idx & 4095;
        int in = j >> 6, out = j & 63;
        g_M[br][b][j] = ker[br][(((out >> 3) - (in >> 3)) & 7) * 8 +
                               (((out & 7) - (in & 7)) & 7)];
    }
}

// ---------------- K1b: weight fp32 -> bf16 hi/lo -----------------------------
__global__ void k_wconv(const float* __restrict__ w,
                        __nv_bfloat16* __restrict__ h,
                        __nv_bfloat16* __restrict__ l, int n)
{
    int i = blockIdx.x * 256 + threadIdx.x;
    if (i >= n) return;
    __nv_bfloat16 hh, ll;
    splitbf(w[i], hh, ll);
    h[i] = hh; l[i] = ll;
}

// ---------------- K2: GroupNorm stats ---------------------------------------
__global__ void __launch_bounds__(256) k_gnstats(const float* __restrict__ x, int gi)
{
    int g = blockIdx.x, b = blockIdx.y;
    const float* p = x + ((size_t)b * 192 + g * 6) * 4096;
    float s = 0.f, s2 = 0.f;
    for (int i = threadIdx.x; i < 24576; i += 256) {
        float v = p[i]; s += v; s2 = fmaf(v, v, s2);
    }
    #pragma unroll
    for (int o = 16; o; o >>= 1) {
        s += __shfl_xor_sync(~0u, s, o); s2 += __shfl_xor_sync(~0u, s2, o);
    }
    __shared__ float sh[2][8];
    int wid = threadIdx.x >> 5;
    if (!(threadIdx.x & 31)) { sh[0][wid] = s; sh[1][wid] = s2; }
    __syncthreads();
    if (threadIdx.x < 32) {
        s  = (threadIdx.x < 8) ? sh[0][threadIdx.x] : 0.f;
        s2 = (threadIdx.x < 8) ? sh[1][threadIdx.x] : 0.f;
        #pragma unroll
        for (int o = 4; o; o >>= 1) {
            s += __shfl_xor_sync(~0u, s, o); s2 += __shfl_xor_sync(~0u, s2, o);
        }
        if (!threadIdx.x) {
            float m = s * (1.f / 24576.f);
            float var = s2 * (1.f / 24576.f) - m * m;
            g_gn[gi][b][g] = make_float2(m, rsqrtf(var + 1e-5f));
        }
    }
}

// ---------------- K3: GN apply + adafm patch GEMM + scatter (bf16 pair out) -
template <int MODE>
__global__ void __launch_bounds__(256) k_adafm(
    const float* __restrict__ src,
    const float* __restrict__ gw, const float* __restrict__ gbv)
{
    extern __shared__ float sm[];
    float* Xs = sm;               // 64 x 196
    float* Ms = sm + 64 * 196;    // 4096
    float* ga = Ms + 4096;        // 192
    float* gb = ga + 192;         // 192
    int patch = blockIdx.x, b = blockIdx.y;
    int py = patch >> 3, px = patch & 7, tid = threadIdx.x;

    if (tid < 192) {
        float2 st = g_gn[MODE][b][tid / 6];
        float a = st.y * gw[tid];
        ga[tid] = a; gb[tid] = gbv[tid] - st.x * a;
    }
    for (int i = tid; i < 4096; i += 256) Ms[i] = g_M[MODE][b][i];
    __syncthreads();

    int u = tid >> 5, cl = tid & 31;
    const float* sb = src + ((size_t)b * 192) * 4096 + (py * 8 + u) * 64 + px * 8;
    #pragma unroll
    for (int cb = 0; cb < 6; cb++) {
        int c = cb * 32 + cl;
        const float* pr = sb + (size_t)c * 4096;
        float4 v0 = *(const float4*)pr;
        float4 v1 = *(const float4*)(pr + 4);
        float a = ga[c], o = gb[c];
        float vv[8] = {v0.x, v0.y, v0.z, v0.w, v1.x, v1.y, v1.z, v1.w};
        #pragma unroll
        for (int j = 0; j < 8; j++)
            Xs[(u * 8 + j) * 196 + c] = fmaf(vv[j], a, o);
    }
    __syncthreads();

    int p = tid & 63, cg = tid >> 6;
    float4 acc[12];
    #pragma unroll
    for (int j = 0; j < 12; j++) acc[j] = make_float4(0.f, 0.f, 0.f, 0.f);
    for (int uu = 0; uu < 64; uu++) {
        float m = Ms[uu * 64 + p];
        const float4* xr = (const float4*)(Xs + uu * 196) + cg * 12;
        #pragma unroll
        for (int j = 0; j < 12; j++) {
            float4 xv = xr[j];
            acc[j].x = fmaf(m, xv.x, acc[j].x);
            acc[j].y = fmaf(m, xv.y, acc[j].y);
            acc[j].z = fmaf(m, xv.z, acc[j].z);
            acc[j].w = fmaf(m, xv.w, acc[j].w);
        }
    }
    int hh = py * 8 + (p >> 3), ww = px * 8 + (p & 7);
    size_t off;
    if (MODE == 0) {
        int hh2 = (hh + 60) & 63, ww2 = (ww + 60) & 63;
        int win = ((hh2 >> 3) << 3) | (ww2 >> 3);
        int nn  = ((hh2 & 7) << 3) | (ww2 & 7);
        off = (((size_t)(b * 64 + win) * 64 + nn) * 192) + cg * 48;
    } else {
        off = (((size_t)b * 4096 + hh * 64 + ww) * 192) + cg * 48;
    }
    #pragma unroll
    for (int j = 0; j < 12; j++) {
        float4 v = acc[j];
        __nv_bfloat16 h0, h1, h2, h3, l0, l1, l2, l3;
        splitbf(v.x, h0, l0); splitbf(v.y, h1, l1);
        splitbf(v.z, h2, l2); splitbf(v.w, h3, l3);
        *(ushort4*)(g_ah + off + j * 4) = make_ushort4(
            __bfloat16_as_ushort(h0), __bfloat16_as_ushort(h1),
            __bfloat16_as_ushort(h2), __bfloat16_as_ushort(h3));
        *(ushort4*)(g_al + off + j * 4) = make_ushort4(
            __bfloat16_as_ushort(l0), __bfloat16_as_ushort(l1),
            __bfloat16_as_ushort(l2), __bfloat16_as_ushort(l3));
    }
}

// ---------------- K4: pipelined bf16-pair tensor GEMM ------------------------
// C[m][n] = sum_k A[m][k]*W[n][k]; A,W pre-split bf16 hi/lo. Block 128x64, k-tile 32.
// EPI 0: +bias -> fp32 | 1: +bias GELU -> bf16 pair | 2: +bias win-rev+roll+res
// EPI 3: +bias chan-major + res
template <int EPI>
__global__ void __launch_bounds__(256, 2) k_bgemm(
    const __nv_bfloat16* __restrict__ Ah, const __nv_bfloat16* __restrict__ Al,
    const __nv_bfloat16* __restrict__ Wh, const __nv_bfloat16* __restrict__ Wl,
    const float* __restrict__ bias, float* __restrict__ Cf,
    __nv_bfloat16* __restrict__ Ch, __nv_bfloat16* __restrict__ Cl,
    int K, int N, const float* __restrict__ res)
{
    extern __shared__ __nv_bfloat16 smem[];
    const int ASZ = 128 * KSTR, BSZ = 64 * KSTR;
    const int STG = 2 * ASZ + 2 * BSZ;   // elems per stage

    int m0 = blockIdx.y * 128, n0 = blockIdx.x * 64;
    int tid = threadIdx.x, lane = tid & 31, wid = tid >> 5;
    int wm = (wid & 3) * 32, wn = (wid >> 2) * 32;

    const __nv_bfloat16* Abh = Ah + (size_t)m0 * K;
    const __nv_bfloat16* Abl = Al + (size_t)m0 * K;
    const __nv_bfloat16* Bbh = Wh + (size_t)n0 * K;
    const __nv_bfloat16* Bbl = Wl + (size_t)n0 * K;
    int KT = K >> 5;

    float c[2][4][4];
    #pragma unroll
    for (int mt = 0; mt < 2; mt++)
        #pragma unroll
        for (int nt = 0; nt < 4; nt++)
            #pragma unroll
            for (int i = 0; i < 4; i++) c[mt][nt][i] = 0.f;

    auto fill = [&](int kt, int st) {
        __nv_bfloat16* base = smem + st * STG;
        int k0 = kt * 32;
        #pragma unroll
        for (int r = 0; r < 2; r++) {
            int e = tid * 2 + r, row = e >> 2, ch = e & 3;
            unsigned d = su32(base + row * KSTR + ch * 8);
            size_t srcoff = (size_t)row * K + k0 + ch * 8;
            cpasync16(d, Abh + srcoff);
            cpasync16(d + ASZ * 2, Abl + srcoff);
        }
        {
            int row = tid >> 2, ch = tid & 3;
            unsigned d = su32(base + 2 * ASZ + row * KSTR + ch * 8);
            size_t srcoff = (size_t)row * K + k0 + ch * 8;
            cpasync16(d, Bbh + srcoff);
            cpasync16(d + BSZ * 2, Bbl + srcoff);
        }
        cpcommit();
    };

    fill(0, 0);
    for (int kt = 0; kt < KT; kt++) {
        if (kt + 1 < KT) { fill(kt + 1, (kt + 1) & 1); cpwait<1>(); }
        else             { cpwait<0>(); }
        __syncthreads();

        const __nv_bfloat16* base = smem + (kt & 1) * STG;
        unsigned sAh = su32(base);
        unsigned sAl = sAh + ASZ * 2;
        unsigned sBh = su32(base + 2 * ASZ);
        unsigned sBl = sBh + BSZ * 2;

        unsigned ah[2][2][4], al[2][2][4];
        #pragma unroll
        for (int mt = 0; mt < 2; mt++)
            #pragma unroll
            for (int kk = 0; kk < 2; kk++) {
                int row = wm + mt * 16 + (lane & 15);
                int col = kk * 16 + ((lane & 16) ? 8 : 0);
                unsigned off = (unsigned)((row * KSTR + col) * 2);
                ldsm4(sAh + off, ah[mt][kk][0], ah[mt][kk][1], ah[mt][kk][2], ah[mt][kk][3]);
                ldsm4(sAl + off, al[mt][kk][0], al[mt][kk][1], al[mt][kk][2], al[mt][kk][3]);
            }
        #pragma unroll
        for (int kk = 0; kk < 2; kk++) {
            unsigned bh[4][2], bl[4][2];
            #pragma unroll
            for (int ntp = 0; ntp < 2; ntp++) {
                int row = wn + ntp * 16 + ((lane & 16) ? 8 : 0) + (lane & 7);
                int col = kk * 16 + ((lane & 8) ? 8 : 0);
                unsigned off = (unsigned)((row * KSTR + col) * 2);
                unsigned r0, r1, r2, r3;
                ldsm4(sBh + off, r0, r1, r2, r3);
                bh[ntp * 2][0] = r0; bh[ntp * 2][1] = r1;
                bh[ntp * 2 + 1][0] = r2; bh[ntp * 2 + 1][1] = r3;
                ldsm4(sBl + off, r0, r1, r2, r3);
                bl[ntp * 2][0] = r0; bl[ntp * 2][1] = r1;
                bl[ntp * 2 + 1][0] = r2; bl[ntp * 2 + 1][1] = r3;
            }
            #pragma unroll
            for (int mt = 0; mt < 2; mt++)
                #pragma unroll
                for (int nt = 0; nt < 4; nt++) {
                    mma16816(c[mt][nt], ah[mt][kk], bh[nt]);
                    mma16816(c[mt][nt], ah[mt][kk], bl[nt]);
                    mma16816(c[mt][nt], al[mt][kk], bh[nt]);
                }
        }
        __syncthreads();
    }

    // epilogue: row = m0+wm+mt*16+(lane>>2)+h*8, col = n0+wn+nt*8+(lane&3)*2
    int g = lane >> 2, tg = lane & 3;
    #pragma unroll
    for (int nt = 0; nt < 4; nt++) {
        int cb = n0 + wn + nt * 8 + tg * 2;
        float2 bv = *(const float2*)(bias + cb);
        #pragma unroll
        for (int mt = 0; mt < 2; mt++)
            #pragma unroll
            for (int h = 0; h < 2; h++) {
                int m = m0 + wm + mt * 16 + g + h * 8;
                float v0 = c[mt][nt][h * 2 + 0] + bv.x;
                float v1 = c[mt][nt][h * 2 + 1] + bv.y;
                if (EPI == 0) {
                    *(float2*)(Cf + (size_t)m * N + cb) = make_float2(v0, v1);
                } else if (EPI == 1) {
                    float g0 = 0.5f * v0 * (1.f + erff(v0 * 0.70710678118654752f));
                    float g1 = 0.5f * v1 * (1.f + erff(v1 * 0.70710678118654752f));
                    __nv_bfloat16 h0, h1, l0, l1;
                    splitbf(g0, h0, l0); splitbf(g1, h1, l1);
                    unsigned hp = (unsigned)__bfloat16_as_ushort(h0) |
                                  ((unsigned)__bfloat16_as_ushort(h1) << 16);
                    unsigned lp = (unsigned)__bfloat16_as_ushort(l0) |
                                  ((unsigned)__bfloat16_as_ushort(l1) << 16);
                    *(unsigned*)(Ch + (size_t)m * N + cb) = hp;
                    *(unsigned*)(Cl + (size_t)m * N + cb) = lp;
                } else if (EPI == 2) {
                    int b = m >> 12, win = (m >> 6) & 63, nn = m & 63;
                    int hh = ((((win >> 3) << 3) + (nn >> 3)) + 4) & 63;
                    int ww = ((((win & 7) << 3) + (nn & 7)) + 4) & 63;
                    size_t base2 = ((size_t)b * 192) * 4096 + hh * 64 + ww;
                    size_t i0 = base2 + (size_t)cb * 4096;
                    size_t i1 = base2 + (size_t)(cb + 1) * 4096;
                    Cf[i0] = res[i0] + v0;
                    Cf[i1] = res[i1] + v1;
                } else {
                    int b = m >> 12, pix = m & 4095;
                    size_t i0 = ((size_t)(b * 192 + cb)) * 4096 + pix;
                    size_t i1 = i0 + 4096;
                    Cf[i0] = res[i0] + v0;
                    Cf[i1] = res[i1] + v1;
                }
            }
    }
}

// ---------------- K5: fused window attention (bf16 pair out) -----------------
__global__ void __launch_bounds__(64) k_attn(
    const float* __restrict__ qkv, const float* __restrict__ rpb)
{
    int w = blockIdx.x, head = blockIdx.y, n = threadIdx.x;
    __shared__ float Ks[64 * 32], Vs[64 * 32], Pr[64 * 64], Br[225];
    __shared__ int Cat[64];

    const float* base = qkv + (size_t)w * 64 * 576 + head * 32;
    {
        const float4* kp = (const float4*)(base + (size_t)n * 576 + 192);
        const float4* vp = (const float4*)(base + (size_t)n * 576 + 384);
        float4* kd = (float4*)(Ks + n * 32);
        float4* vd = (float4*)(Vs + n * 32);
        #pragma unroll
        for (int i = 0; i < 8; i++) { kd[i] = kp[i]; vd[i] = vp[i]; }
    }
    for (int i = n; i < 225; i += 64) Br[i] = rpb[i * 6 + head];
    {
        int win = w & 63;
        int hh2 = ((win >> 3) << 3) + (n >> 3);
        int ww2 = ((win & 7) << 3) + (n & 7);
        int ch = hh2 < 56 ? 0 : (hh2 < 60 ? 1 : 2);
        int cw = ww2 < 56 ? 0 : (ww2 < 60 ? 1 : 2);
        Cat[n] = ch * 3 + cw;
    }
    float q[32];
    {
        const float4* qp = (const float4*)(base + (size_t)n * 576);
        #pragma unroll
        for (int i = 0; i < 8; i++) {
            float4 v = qp[i];
            q[i * 4 + 0] = v.x * SCALE_Q; q[i * 4 + 1] = v.y * SCALE_Q;
            q[i * 4 + 2] = v.z * SCALE_Q; q[i * 4 + 3] = v.w * SCALE_Q;
        }
    }
    __syncthreads();

    int rn = n >> 3, cn = n & 7, mycat = Cat[n];
    float mx = -1e30f;
    for (int m = 0; m < 64; m++) {
        float d = 0.f;
        const float* kr = Ks + m * 32;
        #pragma unroll
        for (int i = 0; i < 32; i++) d = fmaf(q[i], kr[i], d);
        d += Br[(rn - (m >> 3) + 7) * 15 + (cn - (m & 7) + 7)];
        if (Cat[m] != mycat) d -= 100.f;
        Pr[m * 64 + n] = d;
        mx = fmaxf(mx, d);
    }
    float sum = 0.f;
    for (int m = 0; m < 64; m++) {
        float e = __expf(Pr[m * 64 + n] - mx);
        Pr[m * 64 + n] = e;
        sum += e;
    }
    float inv = 1.f / sum;
    float acc[32];
    #pragma unroll
    for (int i = 0; i < 32; i++) acc[i] = 0.f;
    for (int m = 0; m < 64; m++) {
        float p = Pr[m * 64 + n];
        const float* vr = Vs + m * 32;
        #pragma unroll
        for (int i = 0; i < 32; i++) acc[i] = fmaf(p, vr[i], acc[i]);
    }
    size_t off = ((size_t)w * 64 + n) * 192 + head * 32;
    #pragma unroll
    for (int i = 0; i < 8; i++) {
        __nv_bfloat16 h0, h1, h2, h3, l0, l1, l2, l3;
        splitbf(acc[i * 4 + 0] * inv, h0, l0);
        splitbf(acc[i * 4 + 1] * inv, h1, l1);
        splitbf(acc[i * 4 + 2] * inv, h2, l2);
        splitbf(acc[i * 4 + 3] * inv, h3, l3);
        *(ushort4*)(g_ah + off + i * 4) = make_ushort4(
            __bfloat16_as_ushort(h0), __bfloat16_as_ushort(h1),
            __bfloat16_as_ushort(h2), __bfloat16_as_ushort(h3));
        *(ushort4*)(g_al + off + i * 4) = make_ushort4(
            __bfloat16_as_ushort(l0), __bfloat16_as_ushort(l1),
            __bfloat16_as_ushort(l2), __bfloat16_as_ushort(l3));
    }
}

// ---------------- launch ------------------------------------------------------
extern "C" void kernel_launch(void* const* d_in, const int* in_sizes, int n_in,
                              void* d_out, int out_size)
{
    const float* x    = (const float*)d_in[0];
    const float* t    = (const float*)d_in[1];
    const float* n1w  = (const float*)d_in[2];
    const float* n1b  = (const float*)d_in[3];
    const float* qkvw = (const float*)d_in[4];
    const float* qkvb = (const float*)d_in[5];
    const float* rpb  = (const float*)d_in[6];
    const float* pw   = (const float*)d_in[7];
    const float* pb   = (const float*)d_in[8];
    const float* n2w  = (const float*)d_in[9];
    const float* n2b  = (const float*)d_in[10];
    const float* f1w  = (const float*)d_in[11];
    const float* f1b  = (const float*)d_in[12];
    const float* f2w  = (const float*)d_in[13];
    const float* f2b  = (const float*)d_in[14];
    const float* amw  = (const float*)d_in[15];
    const float* amb  = (const float*)d_in[16];
    const float* alw  = (const float*)d_in[17];
    const float* alb  = (const float*)d_in[18];
    float* out = (float*)d_out;

    float *qkvf, *x2;
    __nv_bfloat16 *ah, *al, *bh, *bl, *wh, *wl;
    cudaGetSymbolAddress((void**)&qkvf, g_qkv);
    cudaGetSymbolAddress((void**)&x2,   g_x2v);
    cudaGetSymbolAddress((void**)&ah,   g_ah);
    cudaGetSymbolAddress((void**)&al,   g_al);
    cudaGetSymbolAddress((void**)&bh,   g_bh);
    cudaGetSymbolAddress((void**)&bl,   g_bl);
    cudaGetSymbolAddress((void**)&wh,   g_wh);
    cudaGetSymbolAddress((void**)&wl,   g_wl);

    const int ADAFM_SMEM = (64 * 196 + 4096 + 384) * 4;
    const int GEMM_SMEM  = 2 * (2 * 128 * KSTR + 2 * 64 * KSTR) * 2;  // 61440 B
    static int attr_done = 0;
    if (!attr_done) {
        cudaFuncSetAttribute(k_adafm<0>, cudaFuncAttributeMaxDynamicSharedMemorySize, ADAFM_SMEM);
        cudaFuncSetAttribute(k_adafm<1>, cudaFuncAttributeMaxDynamicSharedMemorySize, ADAFM_SMEM);
        cudaFuncSetAttribute(k_bgemm<0>, cudaFuncAttributeMaxDynamicSharedMemorySize, GEMM_SMEM);
        cudaFuncSetAttribute(k_bgemm<1>, cudaFuncAttributeMaxDynamicSharedMemorySize, GEMM_SMEM);
        cudaFuncSetAttribute(k_bgemm<2>, cudaFuncAttributeMaxDynamicSharedMemorySize, GEMM_SMEM);
        cudaFuncSetAttribute(k_bgemm<3>, cudaFuncAttributeMaxDynamicSharedMemorySize, GEMM_SMEM);
        attr_done = 1;
    }

    k_prep<<<32, 256>>>(t, amw, amb, alw, alb);
    k_wconv<<<432, 256>>>(qkvw, wh, wl, 110592);
    k_wconv<<<144, 256>>>(pw,   wh + 110592, wl + 110592, 36864);
    k_wconv<<<576, 256>>>(f1w,  wh + 147456, wl + 147456, 147456);
    k_wconv<<<576, 256>>>(f2w,  wh + 294912, wl + 294912, 147456);

    k_gnstats<<<dim3(32, 32), 256>>>(x, 0);
    k_adafm<0><<<dim3(64, 32), 256, ADAFM_SMEM>>>(x, n1w, n1b);
    // qkv: (131072 x 192) @ (576 x 192)^T -> fp32
    k_bgemm<0><<<dim3(9, 1024), 256, GEMM_SMEM>>>(ah, al, wh, wl, qkvb,
                                                  qkvf, nullptr, nullptr, 192, 576, nullptr);
    k_attn<<<dim3(2048, 6), 64>>>(qkvf, rpb);
    // proj + window reverse + roll + residual -> x2
    k_bgemm<2><<<dim3(3, 1024), 256, GEMM_SMEM>>>(ah, al, wh + 110592, wl + 110592, pb,
                                                  x2, nullptr, nullptr, 192, 192, x);
    k_gnstats<<<dim3(32, 32), 256>>>(x2, 1);
    k_adafm<1><<<dim3(64, 32), 256, ADAFM_SMEM>>>(x2, n2w, n2b);
    // fc1 + GELU -> bf16 pair
    k_bgemm<1><<<dim3(12, 1024), 256, GEMM_SMEM>>>(ah, al, wh + 147456, wl + 147456, f1b,
                                                   nullptr, bh, bl, 192, 768, nullptr);
    // fc2 + residual scatter -> out
    k_bgemm<3><<<dim3(3, 1024), 256, GEMM_SMEM>>>(bh, bl, wh + 294912, wl + 294912, f2b,
                                                  out, nullptr, nullptr, 768, 192, x2);
}